// round 1
// baseline (speedup 1.0000x reference)
#include <cuda_runtime.h>

// LePEAttention: out = (Q K^T) V * (2/sqrt(32))  per (t, b, window, head)
// Associativity: out = Q (K^T V) * s.  M = K^T V is 32x32 per batch.
// Shapes: q,k,v: (4,2,256,56,56) f32.  H_NUM=1, W_NUM=2 -> windows split W into [0,28) [28,56).
// heads=8, d=32.  128 batches total.

#define HW     3136
#define WW     56
#define WCOL   28
#define NB     128      // 4*2*2*8
#define NCHUNK 14       // 56 rows / 4 rows per chunk
#define ROWPC  4
#define SROW   29       // padded row stride in float4 units (28 data + 1): 29 % 8 = 5, coprime -> conflict-free
#define SCALE2 0.35355339059327373f   // 2 / sqrt(32)

__device__ float g_part[NB * NCHUNK * 1024];  // 7.3 MB scratch
__device__ float g_M[NB * 1024];

#define FFMA2(d, a, b, c) \
    asm("fma.rn.f32x2 %0, %1, %2, %3;" : "=l"(d) : "l"(a), "l"(b), "l"(c))

__device__ __forceinline__ unsigned long long pack2(float x, float y) {
    unsigned long long r;
    asm("mov.b64 %0, {%1,%2};" : "=l"(r) : "f"(x), "f"(y));
    return r;
}
__device__ __forceinline__ float2 unpack2(unsigned long long a) {
    float2 f;
    asm("mov.b64 {%0,%1}, %2;" : "=f"(f.x), "=f"(f.y) : "l"(a));
    return f;
}

// ---------------- Pass 1: partial M = K^T V per (batch, 4-row chunk) ----------------
__global__ __launch_bounds__(256) void p1(const float* __restrict__ K,
                                          const float* __restrict__ V) {
    __shared__ float4 sK[32 * SROW];
    __shared__ float4 sV[32 * SROW];
    __shared__ float  sRed[3 * 64 * 16];

    const int tid   = threadIdx.x;
    const int batch = blockIdx.y;
    const int chunk = blockIdx.x;
    const int h   = batch & 7;
    const int win = (batch >> 3) & 1;
    const int tb  = batch >> 4;              // t*2+b, 0..7
    const int r0  = chunk * ROWPC;

    // float4-unit base: channel block start + window column offset
    const int base4 = (tb * 256 + h * 32) * (HW / 4) + win * (WCOL / 4);
    const float4* Kp = (const float4*)K;
    const float4* Vp = (const float4*)V;

    // Stage 32 ch x 28 float4 units (4 rows x 7 units) for both K and V.
    #pragma unroll
    for (int it = 0; it < 7; ++it) {
        int i = tid + it * 256;              // 0..1791
        bool isv = i >= 896;
        int ii = isv ? i - 896 : i;
        int ch = ii / 28;
        int u  = ii - ch * 28;
        int r  = u / 7;
        int cu = u - r * 7;
        int gi = base4 + ch * (HW / 4) + (r0 + r) * (WW / 4) + cu;
        float4 val = isv ? Vp[gi] : Kp[gi];
        (isv ? sV : sK)[ch * SROW + u] = val;
    }
    __syncthreads();

    // 4 p-groups of 64 threads; thread owns M[d1g+8i][d2g+8j], i,j in 0..3
    const int g   = tid >> 6;
    const int rr  = tid & 63;
    const int d1g = rr >> 3;
    const int d2g = rr & 7;

    unsigned long long acc[4][4][2];
    #pragma unroll
    for (int i = 0; i < 4; i++)
        #pragma unroll
        for (int j = 0; j < 4; j++) { acc[i][j][0] = 0ull; acc[i][j][1] = 0ull; }

    const int p0 = g * 7;
    #pragma unroll
    for (int pp = 0; pp < 7; ++pp) {
        const int p4 = p0 + pp;
        ulonglong2 kf[4], vf[4];
        #pragma unroll
        for (int i = 0; i < 4; i++)
            kf[i] = *reinterpret_cast<const ulonglong2*>(&sK[(d1g + 8 * i) * SROW + p4]);
        #pragma unroll
        for (int j = 0; j < 4; j++)
            vf[j] = *reinterpret_cast<const ulonglong2*>(&sV[(d2g + 8 * j) * SROW + p4]);
        #pragma unroll
        for (int i = 0; i < 4; i++)
            #pragma unroll
            for (int j = 0; j < 4; j++) {
                FFMA2(acc[i][j][0], kf[i].x, vf[j].x, acc[i][j][0]);
                FFMA2(acc[i][j][1], kf[i].y, vf[j].y, acc[i][j][1]);
            }
    }

    float res[4][4];
    #pragma unroll
    for (int i = 0; i < 4; i++)
        #pragma unroll
        for (int j = 0; j < 4; j++) {
            float2 a = unpack2(acc[i][j][0]);
            float2 b = unpack2(acc[i][j][1]);
            res[i][j] = (a.x + a.y) + (b.x + b.y);
        }

    if (g) {
        float* dst = &sRed[((g - 1) * 64 + rr) * 16];
        #pragma unroll
        for (int i = 0; i < 4; i++)
            #pragma unroll
            for (int j = 0; j < 4; j++) dst[i * 4 + j] = res[i][j];
    }
    __syncthreads();
    if (!g) {
        float* o = &g_part[(batch * NCHUNK + chunk) << 10];
        #pragma unroll
        for (int i = 0; i < 4; i++)
            #pragma unroll
            for (int j = 0; j < 4; j++) {
                float s = res[i][j];
                #pragma unroll
                for (int gg = 0; gg < 3; gg++)
                    s += sRed[(gg * 64 + rr) * 16 + i * 4 + j];
                o[(d1g + 8 * i) * 32 + (d2g + 8 * j)] = s;
            }
    }
}

// ---------------- Pass 1b: deterministic chunk reduction, folds in scale ----------------
__global__ void p1r() {
    int idx = blockIdx.x * 256 + threadIdx.x;   // 0..131071
    int b = idx >> 10;
    int e = idx & 1023;
    float s = 0.f;
    #pragma unroll
    for (int c = 0; c < NCHUNK; c++)
        s += g_part[((b * NCHUNK + c) << 10) + e];
    g_M[idx] = s * SCALE2;
}

// ---------------- Pass 2: out = Q @ M (scale pre-folded into M) ----------------
__global__ __launch_bounds__(224) void p2(const float* __restrict__ Q,
                                          float* __restrict__ O) {
    __shared__ float sM[1024];
    const int tid   = threadIdx.x;
    const int batch = blockIdx.y;
    const int chunk = blockIdx.x;

    for (int i = tid; i < 1024; i += 224) sM[i] = g_M[(batch << 10) + i];
    __syncthreads();

    const int h   = batch & 7;
    const int win = (batch >> 3) & 1;
    const int tb  = batch >> 4;

    const int p = chunk * 224 + tid;   // 0..1567, exact (7*224)
    const int r = p / 28;
    const int c = p - r * 28;
    const int base = (tb * 256 + h * 32) * HW + r * WW + win * WCOL + c;

    float qv[32];
    #pragma unroll
    for (int d = 0; d < 32; d++) qv[d] = Q[base + d * HW];

    unsigned long long a[16];
    #pragma unroll
    for (int i = 0; i < 16; i++) a[i] = 0ull;

    #pragma unroll
    for (int d1 = 0; d1 < 32; ++d1) {
        unsigned long long qq = pack2(qv[d1], qv[d1]);
        const ulonglong2* Mr = reinterpret_cast<const ulonglong2*>(&sM[d1 * 32]);
        #pragma unroll
        for (int jq = 0; jq < 8; ++jq) {
            ulonglong2 m = Mr[jq];
            FFMA2(a[2 * jq],     qq, m.x, a[2 * jq]);
            FFMA2(a[2 * jq + 1], qq, m.y, a[2 * jq + 1]);
        }
    }

    #pragma unroll
    for (int jq = 0; jq < 8; ++jq) {
        float2 f0 = unpack2(a[2 * jq]);
        float2 f1 = unpack2(a[2 * jq + 1]);
        O[base + (4 * jq + 0) * HW] = f0.x;
        O[base + (4 * jq + 1) * HW] = f0.y;
        O[base + (4 * jq + 2) * HW] = f1.x;
        O[base + (4 * jq + 3) * HW] = f1.y;
    }
}

extern "C" void kernel_launch(void* const* d_in, const int* in_sizes, int n_in,
                              void* d_out, int out_size) {
    const float* q = (const float*)d_in[0];
    const float* k = (const float*)d_in[1];
    const float* v = (const float*)d_in[2];
    float* o = (float*)d_out;
    // v_lamda (d_in[3]) == 1: Cv == C, ignored.

    p1 <<<dim3(NCHUNK, NB), 256>>> (k, v);
    p1r<<<512, 256>>> ();
    p2 <<<dim3(7, NB), 224>>> (q, o);
}

// round 2
// speedup vs baseline: 1.1250x; 1.1250x over previous
#include <cuda_runtime.h>

// LePEAttention: out = (Q K^T) V * (2/sqrt(32)) per (t, b, window, head); no softmax.
// Associativity: out = Q (K^T V) * s.  M = K^T V is 32x32 per batch (128 batches).
// q,k,v: (4,2,256,56,56) f32. H_NUM=1, W_NUM=2 -> W split [0,28) [28,56). heads=8, d=32.

#define HW     3136
#define WW     56
#define NB     128       // 4*2 * 2 windows * 8 heads
#define SROW   29        // padded row stride in float4 units (28+1): conflict-free
#define SCALE2 0.35355339059327373f   // 2/sqrt(32)

#define BUF_F4 (2 * 32 * SROW)        // K + V, one chunk buffer, in float4 units
#define SMEM_BYTES (2 * BUF_F4 * 16)  // 59392: double buffered

__device__ float g_part[NB * 2 * 1024];   // 2 half-partials per batch

#define FFMA2(d, a, b, c) \
    asm("fma.rn.f32x2 %0, %1, %2, %3;" : "=l"(d) : "l"(a), "l"(b), "l"(c))

__device__ __forceinline__ unsigned long long pack2(float x, float y) {
    unsigned long long r;
    asm("mov.b64 %0, {%1,%2};" : "=l"(r) : "f"(x), "f"(y));
    return r;
}
__device__ __forceinline__ float2 unpack2(unsigned long long a) {
    float2 f;
    asm("mov.b64 {%0,%1}, %2;" : "=f"(f.x), "=f"(f.y) : "l"(a));
    return f;
}
__device__ __forceinline__ void cp16(float4* dst, const float4* src) {
    unsigned d = (unsigned)__cvta_generic_to_shared(dst);
    asm volatile("cp.async.ca.shared.global [%0], [%1], 16;" :: "r"(d), "l"(src));
}

// ---------- Pass 1: M_half = K^T V over 7 chunks (28 rows) -- double-buffered ----------
__global__ __launch_bounds__(256, 2) void p1(const float* __restrict__ K,
                                             const float* __restrict__ V) {
    extern __shared__ float4 smem[];   // [2][2][32*SROW] : buf, K/V

    const int tid   = threadIdx.x;
    const int half  = blockIdx.x;      // 0/1 -> rows [0,28) / [28,56)
    const int batch = blockIdx.y;
    const int h   = batch & 7;
    const int win = (batch >> 3) & 1;
    const int tb  = batch >> 4;

    const int base4 = (tb * 256 + h * 32) * (HW / 4) + win * 7;
    const float4* Kp = (const float4*)K;
    const float4* Vp = (const float4*)V;

    // precompute per-thread load slots (7 slots over 1792 = 896 K + 896 V)
    int l_ch[7], l_u[7], l_roff[7];
    bool l_isv[7];
    #pragma unroll
    for (int it = 0; it < 7; ++it) {
        int i = tid + it * 256;
        bool isv = i >= 896;
        int ii = isv ? i - 896 : i;
        int ch = ii / 28;
        int u  = ii - ch * 28;
        int r  = u / 7;
        int cu = u - r * 7;
        l_isv[it] = isv; l_ch[it] = ch; l_u[it] = u;
        l_roff[it] = r * (WW / 4) + cu;
    }

    const int g   = tid >> 6;          // position-group 0..3
    const int rr  = tid & 63;
    const int d1g = rr >> 3;
    const int d2g = rr & 7;

    unsigned long long acc[4][4][2];
    #pragma unroll
    for (int i = 0; i < 4; i++)
        #pragma unroll
        for (int j = 0; j < 4; j++) { acc[i][j][0] = 0ull; acc[i][j][1] = 0ull; }

    // prologue: chunk 0 into buf 0
    {
        const int r0 = half * 28;      // rows in units of 1 (chunk0 rows r0..r0+3)
        #pragma unroll
        for (int it = 0; it < 7; ++it) {
            const float4* src = (l_isv[it] ? Vp : Kp) + base4
                              + l_ch[it] * (HW / 4) + r0 * (WW / 4) + l_roff[it];
            cp16(&smem[(l_isv[it] ? 32 * SROW : 0) + l_ch[it] * SROW + l_u[it]], src);
        }
        asm volatile("cp.async.commit_group;");
    }

    #pragma unroll 1
    for (int c = 0; c < 7; ++c) {
        if (c < 6) {
            const int b1 = (c + 1) & 1;
            const int r0 = half * 28 + (c + 1) * 4;
            #pragma unroll
            for (int it = 0; it < 7; ++it) {
                const float4* src = (l_isv[it] ? Vp : Kp) + base4
                                  + l_ch[it] * (HW / 4) + r0 * (WW / 4) + l_roff[it];
                cp16(&smem[b1 * BUF_F4 + (l_isv[it] ? 32 * SROW : 0)
                           + l_ch[it] * SROW + l_u[it]], src);
            }
            asm volatile("cp.async.commit_group;");
            asm volatile("cp.async.wait_group 1;");
        } else {
            asm volatile("cp.async.wait_group 0;");
        }
        __syncthreads();

        const float4* sK = &smem[(c & 1) * BUF_F4];
        const float4* sV = sK + 32 * SROW;
        const int p0 = g * 7;
        #pragma unroll
        for (int pp = 0; pp < 7; ++pp) {
            const int p4 = p0 + pp;
            ulonglong2 kf[4], vf[4];
            #pragma unroll
            for (int i = 0; i < 4; i++)
                kf[i] = *reinterpret_cast<const ulonglong2*>(&sK[(d1g + 8 * i) * SROW + p4]);
            #pragma unroll
            for (int j = 0; j < 4; j++)
                vf[j] = *reinterpret_cast<const ulonglong2*>(&sV[(d2g + 8 * j) * SROW + p4]);
            #pragma unroll
            for (int i = 0; i < 4; i++)
                #pragma unroll
                for (int j = 0; j < 4; j++) {
                    FFMA2(acc[i][j][0], kf[i].x, vf[j].x, acc[i][j][0]);
                    FFMA2(acc[i][j][1], kf[i].y, vf[j].y, acc[i][j][1]);
                }
        }
        __syncthreads();
    }

    float res[4][4];
    #pragma unroll
    for (int i = 0; i < 4; i++)
        #pragma unroll
        for (int j = 0; j < 4; j++) {
            float2 a = unpack2(acc[i][j][0]);
            float2 b = unpack2(acc[i][j][1]);
            res[i][j] = (a.x + a.y) + (b.x + b.y);
        }

    // cross-group reduce via smem (reuse buffer 0; all compute done)
    float* sRed = (float*)smem;   // 3*64*16 floats = 12 KB < buffer
    if (g) {
        float* dst = &sRed[((g - 1) * 64 + rr) * 16];
        #pragma unroll
        for (int i = 0; i < 4; i++)
            #pragma unroll
            for (int j = 0; j < 4; j++) dst[i * 4 + j] = res[i][j];
    }
    __syncthreads();
    if (!g) {
        float* o = &g_part[((batch << 1) | half) << 10];
        #pragma unroll
        for (int i = 0; i < 4; i++)
            #pragma unroll
            for (int j = 0; j < 4; j++) {
                float s = res[i][j];
                #pragma unroll
                for (int gg = 0; gg < 3; gg++)
                    s += sRed[(gg * 64 + rr) * 16 + i * 4 + j];
                o[(d1g + 8 * i) * 32 + (d2g + 8 * j)] = s;
            }
    }
}

// ---------- Pass 2: out = Q @ M (halves reduced + scale folded in sM load) ----------
__global__ __launch_bounds__(224, 4) void p2(const float* __restrict__ Q,
                                             float* __restrict__ O) {
    __shared__ float sM[1024];
    const int tid   = threadIdx.x;
    const int batch = blockIdx.y;
    const int chunk = blockIdx.x;

    {
        const float* gp = &g_part[batch << 11];
        for (int i = tid; i < 1024; i += 224)
            sM[i] = (gp[i] + gp[1024 + i]) * SCALE2;
    }
    __syncthreads();

    const int h   = batch & 7;
    const int win = (batch >> 3) & 1;
    const int tb  = batch >> 4;

    const int p = chunk * 224 + tid;   // 0..1567
    const int r = p / 28;
    const int c = p - r * 28;
    const int base = (tb * 256 + h * 32) * HW + r * WW + win * 28 + c;

    unsigned long long a[16];
    #pragma unroll
    for (int i = 0; i < 16; i++) a[i] = 0ull;

    #pragma unroll
    for (int dc = 0; dc < 2; ++dc) {
        float qv[16];
        #pragma unroll
        for (int d = 0; d < 16; d++) qv[d] = Q[base + (dc * 16 + d) * HW];
        #pragma unroll
        for (int d = 0; d < 16; d++) {
            unsigned long long qq = pack2(qv[d], qv[d]);
            const ulonglong2* Mr =
                reinterpret_cast<const ulonglong2*>(&sM[(dc * 16 + d) * 32]);
            #pragma unroll
            for (int jq = 0; jq < 8; ++jq) {
                ulonglong2 m = Mr[jq];
                FFMA2(a[2 * jq],     qq, m.x, a[2 * jq]);
                FFMA2(a[2 * jq + 1], qq, m.y, a[2 * jq + 1]);
            }
        }
    }

    #pragma unroll
    for (int jq = 0; jq < 8; ++jq) {
        float2 f0 = unpack2(a[2 * jq]);
        float2 f1 = unpack2(a[2 * jq + 1]);
        O[base + (4 * jq + 0) * HW] = f0.x;
        O[base + (4 * jq + 1) * HW] = f0.y;
        O[base + (4 * jq + 2) * HW] = f1.x;
        O[base + (4 * jq + 3) * HW] = f1.y;
    }
}

extern "C" void kernel_launch(void* const* d_in, const int* in_sizes, int n_in,
                              void* d_out, int out_size) {
    const float* q = (const float*)d_in[0];
    const float* k = (const float*)d_in[1];
    const float* v = (const float*)d_in[2];
    float* o = (float*)d_out;
    // v_lamda (d_in[3]) == 1: Cv == C.

    cudaFuncSetAttribute(p1, cudaFuncAttributeMaxDynamicSharedMemorySize, SMEM_BYTES);
    p1<<<dim3(2, NB), 256, SMEM_BYTES>>>(k, v);
    p2<<<dim3(7, NB), 224>>>(q, o);
}